// round 11
// baseline (speedup 1.0000x reference)
#include <cuda_runtime.h>

// loss = ||F^T F - S^T S||_F^2 * 2^-38,  F/S = [ch=64, hw=8192] channel-major.
// Fused persistent kernel, 128 blocks x 512 threads, one block per SM.
//   Phase 1: 64x64 Gram-diff partial over 64 i's (f32x2 packed FMA).
//   Barrier 1: epoch-sense flag array, parallel poll (no atomics).
//   Phase 2: 32 Gram entries per block, fixed-order sums, square, block-sum.
//   Finish: blocks 1..127 exit; block 0 polls flag2 and does the final fold.

#define CH    64
#define HW    8192
#define IPB   64
#define NBLK  (HW / IPB)   // 128
#define GELEM (CH * CH)    // 4096
#define PAD   68           // row stride: 272B, every row 16B-aligned

typedef unsigned long long u64;

__device__ float    g_partials[NBLK * GELEM];
__device__ float    g_bp[NBLK];
__device__ unsigned g_flag1[NBLK];
__device__ unsigned g_flag2[NBLK];
__device__ unsigned g_epoch;    // bumped once per launch by block 0 at the end

__device__ __forceinline__ u64 fma2(u64 a, u64 b, u64 c) {
    u64 d;
    asm("fma.rn.f32x2 %0, %1, %2, %3;" : "=l"(d) : "l"(a), "l"(b), "l"(c));
    return d;
}
__device__ __forceinline__ u64 dup2(float x) {
    u64 r;
    asm("mov.b64 %0, {%1, %1};" : "=l"(r) : "f"(x));
    return r;
}

__global__ void __launch_bounds__(512, 1) fused_loss_kernel(const float* __restrict__ A,
                                                            const float* __restrict__ B,
                                                            float* __restrict__ out) {
    __shared__ __align__(16) float fsh[IPB][PAD];
    __shared__ __align__(16) float ssh[IPB][PAD];
    __shared__ float red[16][32];
    __shared__ unsigned sh_target;

    const int tid = threadIdx.x;
    const int bid = blockIdx.x;

    if (tid == 0) sh_target = *(volatile unsigned*)&g_epoch + 1u;

    // ---------------- Phase 1: 64x64 Gram-diff partial over 64 i's ----------
    {
        const int i0 = bid * IPB;
        const int c  = tid >> 3;        // channel 0..63
        const int g0 = tid & 7;         // i-group; thread covers g0 and g0+8

        const float4 fv0 = *reinterpret_cast<const float4*>(A + (size_t)c * HW + i0 + 4 * g0);
        const float4 fv1 = *reinterpret_cast<const float4*>(A + (size_t)c * HW + i0 + 4 * (g0 + 8));
        const float4 sv0 = *reinterpret_cast<const float4*>(B + (size_t)c * HW + i0 + 4 * g0);
        const float4 sv1 = *reinterpret_cast<const float4*>(B + (size_t)c * HW + i0 + 4 * (g0 + 8));
        {
            float f0[4] = {fv0.x, fv0.y, fv0.z, fv0.w};
            float f1[4] = {fv1.x, fv1.y, fv1.z, fv1.w};
            float s0[4] = {sv0.x, sv0.y, sv0.z, sv0.w};
            float s1[4] = {sv1.x, sv1.y, sv1.z, sv1.w};
#pragma unroll
            for (int k = 0; k < 4; ++k) {
                fsh[4 * g0 + k][c]       = f0[k];
                fsh[4 * (g0 + 8) + k][c] = f1[k];
                ssh[4 * g0 + k][c]       = s0[k];
                ssh[4 * (g0 + 8) + k][c] = s1[k];
            }
        }
        __syncthreads();

        const int ty = tid >> 4;   // a-pair (channels 2ty, 2ty+1)
        const int tx = tid & 15;   // b-quad

        u64 accf[4], accs[4];
#pragma unroll
        for (int b = 0; b < 4; ++b) { accf[b] = 0ull; accs[b] = 0ull; }

#pragma unroll 8
        for (int ii = 0; ii < IPB; ++ii) {
            float2     fa  = *reinterpret_cast<const float2*>(&fsh[ii][2 * ty]);
            ulonglong2 fbp = *reinterpret_cast<const ulonglong2*>(&fsh[ii][4 * tx]);
            float2     sa  = *reinterpret_cast<const float2*>(&ssh[ii][2 * ty]);
            ulonglong2 sbp = *reinterpret_cast<const ulonglong2*>(&ssh[ii][4 * tx]);

            u64 fd0 = dup2(fa.x), fd1 = dup2(fa.y);
            u64 sd0 = dup2(sa.x), sd1 = dup2(sa.y);

            accf[0] = fma2(fd0, fbp.x, accf[0]);
            accf[1] = fma2(fd0, fbp.y, accf[1]);
            accf[2] = fma2(fd1, fbp.x, accf[2]);
            accf[3] = fma2(fd1, fbp.y, accf[3]);
            accs[0] = fma2(sd0, sbp.x, accs[0]);
            accs[1] = fma2(sd0, sbp.y, accs[1]);
            accs[2] = fma2(sd1, sbp.x, accs[2]);
            accs[3] = fma2(sd1, sbp.y, accs[3]);
        }

        const u64 neg1 = dup2(-1.0f);
        u64 v0 = fma2(accs[0], neg1, accf[0]);
        u64 v1 = fma2(accs[1], neg1, accf[1]);
        u64 v2 = fma2(accs[2], neg1, accf[2]);
        u64 v3 = fma2(accs[3], neg1, accf[3]);

        float* p = g_partials + (size_t)bid * GELEM;
        float2 d0 = *reinterpret_cast<float2*>(&v0);
        float2 d1 = *reinterpret_cast<float2*>(&v1);
        float2 d2 = *reinterpret_cast<float2*>(&v2);
        float2 d3 = *reinterpret_cast<float2*>(&v3);
        *reinterpret_cast<float4*>(p + (2 * ty + 0) * CH + 4 * tx) =
            make_float4(d0.x, d0.y, d1.x, d1.y);
        *reinterpret_cast<float4*>(p + (2 * ty + 1) * CH + 4 * tx) =
            make_float4(d2.x, d2.y, d3.x, d3.y);
    }

    // ---------------- Barrier 1: flag + parallel poll ------------------------
    __syncthreads();                      // sh_target visible; partial STGs issued
    const unsigned target = sh_target;
    __threadfence();                      // partials visible before flag
    if (tid == 0) *(volatile unsigned*)&g_flag1[bid] = target;
    if (tid < NBLK) {
        volatile unsigned* f = &g_flag1[tid];
        while (*f < target) __nanosleep(64);
    }
    __syncthreads();
    __threadfence();                      // acquire partials

    // ---------------- Phase 2: reduce 32 entries, square, block-sum ----------
    {
        const int lane = tid & 31;        // entry within block's 32 (coalesced)
        const int grp  = tid >> 5;        // 0..15, each sums 8 partial blocks
        const int e    = bid * 32 + lane;

        float s = 0.0f;
#pragma unroll
        for (int k = 0; k < 8; ++k)
            s += g_partials[(size_t)(grp * 8 + k) * GELEM + e];

        red[grp][lane] = s;
        __syncthreads();
#pragma unroll
        for (int off = 8; off > 0; off >>= 1) {
            if (grp < off) red[grp][lane] += red[grp + off][lane];
            __syncthreads();
        }

        if (tid < 32) {
            float tot = red[0][tid];
            float sq  = tot * tot;
#pragma unroll
            for (int off = 16; off > 0; off >>= 1)
                sq += __shfl_down_sync(0xffffffffu, sq, off);
            if (tid == 0) {
                g_bp[bid] = sq;
                __threadfence();
                *(volatile unsigned*)&g_flag2[bid] = target;
            }
        }
    }

    // Blocks 1..127 are done; block 0 finishes.
    if (bid != 0) return;

    if (tid < NBLK) {
        volatile unsigned* f = &g_flag2[tid];
        while (*f < target) __nanosleep(64);
    }
    __syncthreads();
    __threadfence();

    if (tid < 32) {
        volatile float* vb = g_bp;
        float v = vb[tid] + vb[tid + 32] + vb[tid + 64] + vb[tid + 96];
#pragma unroll
        for (int off = 16; off > 0; off >>= 1)
            v += __shfl_down_sync(0xffffffffu, v, off);
        if (tid == 0) {
            out[0] = v * (1.0f / 274877906944.0f);  // * 2^-38 exact
            *(volatile unsigned*)&g_epoch = target; // sense flip for next replay
        }
    }
}

extern "C" void kernel_launch(void* const* d_in, const int* in_sizes, int n_in,
                              void* d_out, int out_size) {
    const float* A = (const float*)d_in[0];
    const float* B = (const float*)d_in[1];
    float* out = (float*)d_out;

    fused_loss_kernel<<<NBLK, 512>>>(A, B, out);
}

// round 12
// speedup vs baseline: 1.0949x; 1.0949x over previous
#include <cuda_runtime.h>

// loss = ||F^T F - S^T S||_F^2 * 2^-38,  F/S = [ch=64, hw=8192] channel-major.
// Fused persistent kernel, 128 blocks x 512 threads, one block per SM.
//   Phase 1: 64x64 Gram-diff partial over 64 i's (f32x2 packed FMA).
//   Barrier: epoch-sense flag array; ONE warp polls via uint4 loads, NO nanosleep,
//            release/acquire ordering (no full MEMBAR.GPU).
//   Phase 2: 32 Gram entries per block, fixed-order sums, square, block-sum.
//   Finish: blocks 1..127 exit; block 0 polls flag2 and folds 128 block sums.

#define CH    64
#define HW    8192
#define IPB   64
#define NBLK  (HW / IPB)   // 128
#define GELEM (CH * CH)    // 4096
#define PAD   68           // row stride: 272B, every row 16B-aligned

typedef unsigned long long u64;

__device__ float g_partials[NBLK * GELEM];
__device__ float g_bp[NBLK];
__device__ __align__(16) unsigned g_flag1[NBLK];
__device__ __align__(16) unsigned g_flag2[NBLK];
__device__ unsigned g_epoch;

__device__ __forceinline__ u64 fma2(u64 a, u64 b, u64 c) {
    u64 d;
    asm("fma.rn.f32x2 %0, %1, %2, %3;" : "=l"(d) : "l"(a), "l"(b), "l"(c));
    return d;
}
__device__ __forceinline__ u64 dup2(float x) {
    u64 r;
    asm("mov.b64 %0, {%1, %1};" : "=l"(r) : "f"(x));
    return r;
}
__device__ __forceinline__ void st_release(unsigned* p, unsigned v) {
    asm volatile("st.global.release.gpu.u32 [%0], %1;" :: "l"(p), "r"(v) : "memory");
}
__device__ __forceinline__ unsigned ld_acquire(const unsigned* p) {
    unsigned v;
    asm volatile("ld.global.acquire.gpu.u32 %0, [%1];" : "=r"(v) : "l"(p) : "memory");
    return v;
}
__device__ __forceinline__ uint4 ld_strong_v4(const unsigned* p) {
    uint4 v;
    asm volatile("ld.global.relaxed.gpu.v4.u32 {%0,%1,%2,%3}, [%4];"
                 : "=r"(v.x), "=r"(v.y), "=r"(v.z), "=r"(v.w) : "l"(p) : "memory");
    return v;
}

// Wait until all NBLK flags reach 'target'. Call with full block; thread t<32
// polls flags 4t..4t+3. Ends with __syncthreads + one acquire load for ordering.
__device__ __forceinline__ void wait_flags(const unsigned* flags, unsigned target, int tid) {
    if (tid < 32) {
        const unsigned* p = flags + 4 * tid;
        for (;;) {
            uint4 f = ld_strong_v4(p);
            unsigned m = f.x < f.y ? f.x : f.y;
            unsigned n = f.z < f.w ? f.z : f.w;
            if ((m < n ? m : n) >= target) break;
        }
        (void)ld_acquire(p);  // acquire: order subsequent reads after flag observe
    }
    __syncthreads();
}

__global__ void __launch_bounds__(512, 1) fused_loss_kernel(const float* __restrict__ A,
                                                            const float* __restrict__ B,
                                                            float* __restrict__ out) {
    __shared__ __align__(16) float fsh[IPB][PAD];
    __shared__ __align__(16) float ssh[IPB][PAD];
    __shared__ float red[16][32];
    __shared__ unsigned sh_target;

    const int tid = threadIdx.x;
    const int bid = blockIdx.x;

    if (tid == 0) sh_target = *(volatile unsigned*)&g_epoch + 1u;

    // ---------------- Phase 1: 64x64 Gram-diff partial over 64 i's ----------
    {
        const int i0 = bid * IPB;
        const int c  = tid >> 3;
        const int g0 = tid & 7;

        const float4 fv0 = *reinterpret_cast<const float4*>(A + (size_t)c * HW + i0 + 4 * g0);
        const float4 fv1 = *reinterpret_cast<const float4*>(A + (size_t)c * HW + i0 + 4 * (g0 + 8));
        const float4 sv0 = *reinterpret_cast<const float4*>(B + (size_t)c * HW + i0 + 4 * g0);
        const float4 sv1 = *reinterpret_cast<const float4*>(B + (size_t)c * HW + i0 + 4 * (g0 + 8));
        {
            float f0[4] = {fv0.x, fv0.y, fv0.z, fv0.w};
            float f1[4] = {fv1.x, fv1.y, fv1.z, fv1.w};
            float s0[4] = {sv0.x, sv0.y, sv0.z, sv0.w};
            float s1[4] = {sv1.x, sv1.y, sv1.z, sv1.w};
#pragma unroll
            for (int k = 0; k < 4; ++k) {
                fsh[4 * g0 + k][c]       = f0[k];
                fsh[4 * (g0 + 8) + k][c] = f1[k];
                ssh[4 * g0 + k][c]       = s0[k];
                ssh[4 * (g0 + 8) + k][c] = s1[k];
            }
        }
        __syncthreads();

        const int ty = tid >> 4;   // a-pair (channels 2ty, 2ty+1)
        const int tx = tid & 15;   // b-quad

        u64 accf[4], accs[4];
#pragma unroll
        for (int b = 0; b < 4; ++b) { accf[b] = 0ull; accs[b] = 0ull; }

#pragma unroll 8
        for (int ii = 0; ii < IPB; ++ii) {
            float2     fa  = *reinterpret_cast<const float2*>(&fsh[ii][2 * ty]);
            ulonglong2 fbp = *reinterpret_cast<const ulonglong2*>(&fsh[ii][4 * tx]);
            float2     sa  = *reinterpret_cast<const float2*>(&ssh[ii][2 * ty]);
            ulonglong2 sbp = *reinterpret_cast<const ulonglong2*>(&ssh[ii][4 * tx]);

            u64 fd0 = dup2(fa.x), fd1 = dup2(fa.y);
            u64 sd0 = dup2(sa.x), sd1 = dup2(sa.y);

            accf[0] = fma2(fd0, fbp.x, accf[0]);
            accf[1] = fma2(fd0, fbp.y, accf[1]);
            accf[2] = fma2(fd1, fbp.x, accf[2]);
            accf[3] = fma2(fd1, fbp.y, accf[3]);
            accs[0] = fma2(sd0, sbp.x, accs[0]);
            accs[1] = fma2(sd0, sbp.y, accs[1]);
            accs[2] = fma2(sd1, sbp.x, accs[2]);
            accs[3] = fma2(sd1, sbp.y, accs[3]);
        }

        const u64 neg1 = dup2(-1.0f);
        u64 v0 = fma2(accs[0], neg1, accf[0]);
        u64 v1 = fma2(accs[1], neg1, accf[1]);
        u64 v2 = fma2(accs[2], neg1, accf[2]);
        u64 v3 = fma2(accs[3], neg1, accf[3]);

        float* p = g_partials + (size_t)bid * GELEM;
        float2 d0 = *reinterpret_cast<float2*>(&v0);
        float2 d1 = *reinterpret_cast<float2*>(&v1);
        float2 d2 = *reinterpret_cast<float2*>(&v2);
        float2 d3 = *reinterpret_cast<float2*>(&v3);
        *reinterpret_cast<float4*>(p + (2 * ty + 0) * CH + 4 * tx) =
            make_float4(d0.x, d0.y, d1.x, d1.y);
        *reinterpret_cast<float4*>(p + (2 * ty + 1) * CH + 4 * tx) =
            make_float4(d2.x, d2.y, d3.x, d3.y);
    }

    // ---------------- Barrier: publish partial, wait for all ------------------
    __syncthreads();                 // all partial STGs issued; sh_target visible
    const unsigned target = sh_target;
    if (tid == 0) st_release(&g_flag1[bid], target);   // orders prior STGs
    wait_flags(g_flag1, target, tid);

    // ---------------- Phase 2: reduce 32 entries, square, block-sum ----------
    {
        const int lane = tid & 31;
        const int grp  = tid >> 5;        // 0..15, each sums 8 partial blocks
        const int e    = bid * 32 + lane;

        float s = 0.0f;
#pragma unroll
        for (int k = 0; k < 8; ++k)
            s += g_partials[(size_t)(grp * 8 + k) * GELEM + e];

        red[grp][lane] = s;
        __syncthreads();
#pragma unroll
        for (int off = 8; off > 0; off >>= 1) {
            if (grp < off) red[grp][lane] += red[grp + off][lane];
            __syncthreads();
        }

        if (tid < 32) {
            float tot = red[0][tid];
            float sq  = tot * tot;
#pragma unroll
            for (int off = 16; off > 0; off >>= 1)
                sq += __shfl_down_sync(0xffffffffu, sq, off);
            if (tid == 0) {
                g_bp[bid] = sq;
                st_release(&g_flag2[bid], target);     // orders g_bp write
            }
        }
    }

    if (bid != 0) return;

    // ---------------- Block 0: final fold ------------------------------------
    wait_flags(g_flag2, target, tid);

    if (tid < 32) {
        volatile float* vb = g_bp;
        float v = vb[tid] + vb[tid + 32] + vb[tid + 64] + vb[tid + 96];
#pragma unroll
        for (int off = 16; off > 0; off >>= 1)
            v += __shfl_down_sync(0xffffffffu, v, off);
        if (tid == 0) {
            out[0] = v * (1.0f / 274877906944.0f);  // * 2^-38 exact
            *(volatile unsigned*)&g_epoch = target; // sense flip for next replay
        }
    }
}

extern "C" void kernel_launch(void* const* d_in, const int* in_sizes, int n_in,
                              void* d_out, int out_size) {
    const float* A = (const float*)d_in[0];
    const float* B = (const float*)d_in[1];
    float* out = (float*)d_out;

    fused_loss_kernel<<<NBLK, 512>>>(A, B, out);
}

// round 13
// speedup vs baseline: 1.3589x; 1.2411x over previous
#include <cuda_runtime.h>

// loss = ||F^T F - S^T S||_F^2 * 2^-38,  F/S = [ch=64, hw=8192] channel-major.
// Two kernels; the stream boundary is the only global sync.
//   K1: 128 blocks x 512 threads, one per SM: 64x64 Gram-diff partial over
//       64 i's (f32x2 packed FMA, swizzle-free padded SMEM, 2a x 4b tiles).
//   K2: 32 blocks x 256 threads: sum 128 partials per Gram entry (fixed order,
//       coalesced, L2-resident), square, block-sum; last block (int-atomic
//       elected, deterministic float order) folds 32 block sums -> out.

#define CH    64
#define HW    8192
#define IPB   64
#define NBLK  (HW / IPB)   // 128
#define GELEM (CH * CH)    // 4096
#define PAD   68           // row stride: 272B, every row 16B-aligned

typedef unsigned long long u64;

__device__ float    g_partials[NBLK * GELEM];
__device__ float    g_bp[32];
__device__ unsigned g_count;   // zero-init; reset by the last K2 block each call

__device__ __forceinline__ u64 fma2(u64 a, u64 b, u64 c) {
    u64 d;
    asm("fma.rn.f32x2 %0, %1, %2, %3;" : "=l"(d) : "l"(a), "l"(b), "l"(c));
    return d;
}
__device__ __forceinline__ u64 dup2(float x) {
    u64 r;
    asm("mov.b64 %0, {%1, %1};" : "=l"(r) : "f"(x));
    return r;
}

__global__ void __launch_bounds__(512, 1) gram_kernel(const float* __restrict__ A,
                                                      const float* __restrict__ B) {
    __shared__ __align__(16) float fsh[IPB][PAD];
    __shared__ __align__(16) float ssh[IPB][PAD];

    const int tid = threadIdx.x;
    const int bid = blockIdx.x;
    const int i0  = bid * IPB;
    const int c   = tid >> 3;       // channel 0..63
    const int g0  = tid & 7;        // i-group; thread covers g0 and g0+8

    const float4 fv0 = *reinterpret_cast<const float4*>(A + (size_t)c * HW + i0 + 4 * g0);
    const float4 fv1 = *reinterpret_cast<const float4*>(A + (size_t)c * HW + i0 + 4 * (g0 + 8));
    const float4 sv0 = *reinterpret_cast<const float4*>(B + (size_t)c * HW + i0 + 4 * g0);
    const float4 sv1 = *reinterpret_cast<const float4*>(B + (size_t)c * HW + i0 + 4 * (g0 + 8));
    {
        float f0[4] = {fv0.x, fv0.y, fv0.z, fv0.w};
        float f1[4] = {fv1.x, fv1.y, fv1.z, fv1.w};
        float s0[4] = {sv0.x, sv0.y, sv0.z, sv0.w};
        float s1[4] = {sv1.x, sv1.y, sv1.z, sv1.w};
#pragma unroll
        for (int k = 0; k < 4; ++k) {
            fsh[4 * g0 + k][c]       = f0[k];
            fsh[4 * (g0 + 8) + k][c] = f1[k];
            ssh[4 * g0 + k][c]       = s0[k];
            ssh[4 * (g0 + 8) + k][c] = s1[k];
        }
    }
    __syncthreads();

    const int ty = tid >> 4;   // a-pair (channels 2ty, 2ty+1)
    const int tx = tid & 15;   // b-quad

    u64 accf[4], accs[4];
#pragma unroll
    for (int b = 0; b < 4; ++b) { accf[b] = 0ull; accs[b] = 0ull; }

#pragma unroll 8
    for (int ii = 0; ii < IPB; ++ii) {
        float2     fa  = *reinterpret_cast<const float2*>(&fsh[ii][2 * ty]);
        ulonglong2 fbp = *reinterpret_cast<const ulonglong2*>(&fsh[ii][4 * tx]);
        float2     sa  = *reinterpret_cast<const float2*>(&ssh[ii][2 * ty]);
        ulonglong2 sbp = *reinterpret_cast<const ulonglong2*>(&ssh[ii][4 * tx]);

        u64 fd0 = dup2(fa.x), fd1 = dup2(fa.y);
        u64 sd0 = dup2(sa.x), sd1 = dup2(sa.y);

        accf[0] = fma2(fd0, fbp.x, accf[0]);
        accf[1] = fma2(fd0, fbp.y, accf[1]);
        accf[2] = fma2(fd1, fbp.x, accf[2]);
        accf[3] = fma2(fd1, fbp.y, accf[3]);
        accs[0] = fma2(sd0, sbp.x, accs[0]);
        accs[1] = fma2(sd0, sbp.y, accs[1]);
        accs[2] = fma2(sd1, sbp.x, accs[2]);
        accs[3] = fma2(sd1, sbp.y, accs[3]);
    }

    const u64 neg1 = dup2(-1.0f);
    u64 v0 = fma2(accs[0], neg1, accf[0]);
    u64 v1 = fma2(accs[1], neg1, accf[1]);
    u64 v2 = fma2(accs[2], neg1, accf[2]);
    u64 v3 = fma2(accs[3], neg1, accf[3]);

    float* p = g_partials + (size_t)bid * GELEM;
    float2 d0 = *reinterpret_cast<float2*>(&v0);
    float2 d1 = *reinterpret_cast<float2*>(&v1);
    float2 d2 = *reinterpret_cast<float2*>(&v2);
    float2 d3 = *reinterpret_cast<float2*>(&v3);
    *reinterpret_cast<float4*>(p + (2 * ty + 0) * CH + 4 * tx) =
        make_float4(d0.x, d0.y, d1.x, d1.y);
    *reinterpret_cast<float4*>(p + (2 * ty + 1) * CH + 4 * tx) =
        make_float4(d2.x, d2.y, d3.x, d3.y);
}

__global__ void __launch_bounds__(256) reduce_kernel(float* __restrict__ out) {
    // Block handles 128 Gram entries. Thread: e = bid*128 + (tid&127),
    // half = tid>>7 sums 64 partials (warp lanes -> consecutive e: coalesced).
    __shared__ float sh[2][128];
    __shared__ float wsq[8];
    __shared__ bool  last;

    const int tid  = threadIdx.x;
    const int bid  = blockIdx.x;
    const int el   = tid & 127;
    const int half = tid >> 7;
    const int e    = bid * 128 + el;

    float s = 0.0f;
#pragma unroll 16
    for (int k = 0; k < 64; ++k)
        s += g_partials[(size_t)(half * 64 + k) * GELEM + e];
    sh[half][el] = s;
    __syncthreads();

    // Square and block-reduce the 128 totals (fixed order everywhere).
    float sq = 0.0f;
    if (tid < 128) {
        float tot = sh[0][tid] + sh[1][tid];
        sq = tot * tot;
    }
#pragma unroll
    for (int off = 16; off > 0; off >>= 1)
        sq += __shfl_down_sync(0xffffffffu, sq, off);
    if ((tid & 31) == 0) wsq[tid >> 5] = sq;
    __syncthreads();

    if (tid == 0) {
        float bsum = wsq[0] + wsq[1] + wsq[2] + wsq[3];  // warps 4..7 contributed 0
        g_bp[bid] = bsum;
        __threadfence();
        last = (atomicAdd(&g_count, 1u) == 31u);
    }
    __syncthreads();

    if (last && tid < 32) {
        __threadfence();
        volatile float* vb = g_bp;
        float v = vb[tid];
#pragma unroll
        for (int off = 16; off > 0; off >>= 1)
            v += __shfl_down_sync(0xffffffffu, v, off);
        if (tid == 0) {
            out[0] = v * (1.0f / 274877906944.0f);  // * 2^-38 exact
            g_count = 0u;                           // reset for next replay
        }
    }
}

extern "C" void kernel_launch(void* const* d_in, const int* in_sizes, int n_in,
                              void* d_out, int out_size) {
    const float* A = (const float*)d_in[0];
    const float* B = (const float*)d_in[1];
    float* out = (float*)d_out;

    gram_kernel<<<NBLK, 512>>>(A, B);
    reduce_kernel<<<32, 256>>>(out);
}

// round 14
// speedup vs baseline: 1.5668x; 1.1530x over previous
#include <cuda_runtime.h>

// loss = ||F^T F - S^T S||_F^2 * 2^-38,  F/S = [ch=64, hw=8192] channel-major.
// Two kernels; stream boundary is the only global sync.
//   K1: 128 blocks x 512 threads (1/SM): 64x64 Gram-diff partial over 64 i's
//       (f32x2 packed FMA, padded SMEM, 2a x 4b tiles).
//   K2: 32 blocks x 512 threads: vectorized partial reduction.
//       Thread (warp w, lane l): sums 8 float4 partials (entries 4q..4q+3,
//       q = 32*bid + l) over partial rows w*8..w*8+7 — 8 independent LDG.128,
//       coalesced 512B per warp. SMEM fold over 16 warps, square, block-sum,
//       last block (int-atomic elected) folds 32 block sums -> out.

#define CH    64
#define HW    8192
#define IPB   64
#define NBLK  (HW / IPB)   // 128 partial Gram matrices
#define GELEM (CH * CH)    // 4096
#define PAD   68           // K1 SMEM row stride: 272B, 16B-aligned rows

typedef unsigned long long u64;

__device__ float    g_partials[NBLK * GELEM];
__device__ float    g_bp[32];
__device__ unsigned g_count;   // zero-init; reset by last K2 block each call

__device__ __forceinline__ u64 fma2(u64 a, u64 b, u64 c) {
    u64 d;
    asm("fma.rn.f32x2 %0, %1, %2, %3;" : "=l"(d) : "l"(a), "l"(b), "l"(c));
    return d;
}
__device__ __forceinline__ u64 dup2(float x) {
    u64 r;
    asm("mov.b64 %0, {%1, %1};" : "=l"(r) : "f"(x));
    return r;
}

__global__ void __launch_bounds__(512, 1) gram_kernel(const float* __restrict__ A,
                                                      const float* __restrict__ B) {
    __shared__ __align__(16) float fsh[IPB][PAD];
    __shared__ __align__(16) float ssh[IPB][PAD];

    const int tid = threadIdx.x;
    const int bid = blockIdx.x;
    const int i0  = bid * IPB;
    const int c   = tid >> 3;       // channel 0..63
    const int g0  = tid & 7;        // i-group; thread covers g0 and g0+8

    const float4 fv0 = *reinterpret_cast<const float4*>(A + (size_t)c * HW + i0 + 4 * g0);
    const float4 fv1 = *reinterpret_cast<const float4*>(A + (size_t)c * HW + i0 + 4 * (g0 + 8));
    const float4 sv0 = *reinterpret_cast<const float4*>(B + (size_t)c * HW + i0 + 4 * g0);
    const float4 sv1 = *reinterpret_cast<const float4*>(B + (size_t)c * HW + i0 + 4 * (g0 + 8));
    {
        float f0[4] = {fv0.x, fv0.y, fv0.z, fv0.w};
        float f1[4] = {fv1.x, fv1.y, fv1.z, fv1.w};
        float s0[4] = {sv0.x, sv0.y, sv0.z, sv0.w};
        float s1[4] = {sv1.x, sv1.y, sv1.z, sv1.w};
#pragma unroll
        for (int k = 0; k < 4; ++k) {
            fsh[4 * g0 + k][c]       = f0[k];
            fsh[4 * (g0 + 8) + k][c] = f1[k];
            ssh[4 * g0 + k][c]       = s0[k];
            ssh[4 * (g0 + 8) + k][c] = s1[k];
        }
    }
    __syncthreads();

    const int ty = tid >> 4;   // a-pair (channels 2ty, 2ty+1)
    const int tx = tid & 15;   // b-quad

    u64 accf[4], accs[4];
#pragma unroll
    for (int b = 0; b < 4; ++b) { accf[b] = 0ull; accs[b] = 0ull; }

#pragma unroll 8
    for (int ii = 0; ii < IPB; ++ii) {
        float2     fa  = *reinterpret_cast<const float2*>(&fsh[ii][2 * ty]);
        ulonglong2 fbp = *reinterpret_cast<const ulonglong2*>(&fsh[ii][4 * tx]);
        float2     sa  = *reinterpret_cast<const float2*>(&ssh[ii][2 * ty]);
        ulonglong2 sbp = *reinterpret_cast<const ulonglong2*>(&ssh[ii][4 * tx]);

        u64 fd0 = dup2(fa.x), fd1 = dup2(fa.y);
        u64 sd0 = dup2(sa.x), sd1 = dup2(sa.y);

        accf[0] = fma2(fd0, fbp.x, accf[0]);
        accf[1] = fma2(fd0, fbp.y, accf[1]);
        accf[2] = fma2(fd1, fbp.x, accf[2]);
        accf[3] = fma2(fd1, fbp.y, accf[3]);
        accs[0] = fma2(sd0, sbp.x, accs[0]);
        accs[1] = fma2(sd0, sbp.y, accs[1]);
        accs[2] = fma2(sd1, sbp.x, accs[2]);
        accs[3] = fma2(sd1, sbp.y, accs[3]);
    }

    const u64 neg1 = dup2(-1.0f);
    u64 v0 = fma2(accs[0], neg1, accf[0]);
    u64 v1 = fma2(accs[1], neg1, accf[1]);
    u64 v2 = fma2(accs[2], neg1, accf[2]);
    u64 v3 = fma2(accs[3], neg1, accf[3]);

    float* p = g_partials + (size_t)bid * GELEM;
    float2 d0 = *reinterpret_cast<float2*>(&v0);
    float2 d1 = *reinterpret_cast<float2*>(&v1);
    float2 d2 = *reinterpret_cast<float2*>(&v2);
    float2 d3 = *reinterpret_cast<float2*>(&v3);
    *reinterpret_cast<float4*>(p + (2 * ty + 0) * CH + 4 * tx) =
        make_float4(d0.x, d0.y, d1.x, d1.y);
    *reinterpret_cast<float4*>(p + (2 * ty + 1) * CH + 4 * tx) =
        make_float4(d2.x, d2.y, d3.x, d3.y);
}

__global__ void __launch_bounds__(512) reduce_kernel(float* __restrict__ out) {
    // Block: 32 entry-quads (128 entries), 16 warps = 16 partial chunks of 8.
    __shared__ float4 sh[16][32];
    __shared__ bool   last;

    const int tid  = threadIdx.x;
    const int bid  = blockIdx.x;
    const int w    = tid >> 5;          // partial chunk 0..15
    const int lane = tid & 31;          // entry-quad within block
    const int q    = bid * 32 + lane;   // global entry-quad 0..1023

    // 8 independent coalesced LDG.128, fixed-order sum.
    const float4* base = reinterpret_cast<const float4*>(g_partials) + q;
    float4 s = make_float4(0.f, 0.f, 0.f, 0.f);
#pragma unroll
    for (int j = 0; j < 8; ++j) {
        float4 v = base[(size_t)(w * 8 + j) * (GELEM / 4)];
        s.x += v.x; s.y += v.y; s.z += v.z; s.w += v.w;
    }
    sh[w][lane] = s;
    __syncthreads();

    // Warp 0: fold 16 chunks per quad (fixed order), square, reduce 32 quads.
    if (tid < 32) {
        float4 t = sh[0][tid];
#pragma unroll
        for (int k = 1; k < 16; ++k) {
            float4 v = sh[k][tid];
            t.x += v.x; t.y += v.y; t.z += v.z; t.w += v.w;
        }
        float sq = t.x * t.x + t.y * t.y + t.z * t.z + t.w * t.w;
#pragma unroll
        for (int off = 16; off > 0; off >>= 1)
            sq += __shfl_down_sync(0xffffffffu, sq, off);
        if (tid == 0) {
            g_bp[bid] = sq;
            __threadfence();
            last = (atomicAdd(&g_count, 1u) == 31u);
        }
    }
    __syncthreads();

    if (last && tid < 32) {
        __threadfence();
        volatile float* vb = g_bp;
        float v = vb[tid];
#pragma unroll
        for (int off = 16; off > 0; off >>= 1)
            v += __shfl_down_sync(0xffffffffu, v, off);
        if (tid == 0) {
            out[0] = v * (1.0f / 274877906944.0f);  // * 2^-38 exact
            g_count = 0u;                           // reset for next replay
        }
    }
}

extern "C" void kernel_launch(void* const* d_in, const int* in_sizes, int n_in,
                              void* d_out, int out_size) {
    const float* A = (const float*)d_in[0];
    const float* B = (const float*)d_in[1];
    float* out = (float*)d_out;

    gram_kernel<<<NBLK, 512>>>(A, B);
    reduce_kernel<<<32, 512>>>(out);
}